// round 17
// baseline (speedup 1.0000x reference)
#include <cuda_runtime.h>
#include <cuda_fp16.h>
#include <cstdint>
#include <math.h>

// ---------------------------------------------------------------------------
// Problem sizes
// ---------------------------------------------------------------------------
constexpr int BBATCH = 8;
constexpr int SEQ    = 2048;
constexpr int DIM    = 1024;

// ---------------------------------------------------------------------------
// Scratch (static device globals — allocation-guard safe)
// ---------------------------------------------------------------------------
__device__ __half g_xh    [(size_t)BBATCH * SEQ * DIM];      // 32 MB
__device__ __half g_qkv   [(size_t)BBATCH * SEQ * 3 * DIM];  // 96 MB (Q|K|V fp16)
__device__ float  g_scores[(size_t)BBATCH * SEQ * SEQ];      // 128 MB fp32
__device__ __half g_w     [(size_t)BBATCH * SEQ * SEQ];      // 64 MB fp16 weights
__device__ __half g_att   [(size_t)BBATCH * SEQ * DIM];      // 32 MB
__device__ __half g_vT    [(size_t)BBATCH * DIM * SEQ];      // 32 MB
__device__ __half g_wqkvT [(size_t)3 * DIM * DIM];           //  6 MB
__device__ __half g_woutT [(size_t)DIM * DIM];               //  2 MB

// ---------------------------------------------------------------------------
// Helpers (baseline PTX only)
// ---------------------------------------------------------------------------
__device__ __forceinline__ uint32_t h2_as_u32(__half2 h) {
    uint32_t u;
    __builtin_memcpy(&u, &h, 4);
    return u;
}

__device__ __forceinline__ uint32_t s2u(const void* p) {
    uint32_t a;
    asm("{ .reg .u64 t; cvta.to.shared.u64 t, %1; cvt.u32.u64 %0, t; }"
        : "=r"(a) : "l"(p));
    return a;
}

__device__ __forceinline__ void cpa16(uint32_t s, const void* g) {
    asm volatile("cp.async.cg.shared.global [%0], [%1], 16;" :: "r"(s), "l"(g));
}

__device__ __forceinline__ void ldsm4(uint32_t r[4], uint32_t addr) {
    asm volatile("ldmatrix.sync.aligned.m8n8.x4.shared.b16 {%0,%1,%2,%3}, [%4];"
                 : "=r"(r[0]), "=r"(r[1]), "=r"(r[2]), "=r"(r[3]) : "r"(addr));
}

// fp16 MMA, fp32 accumulate: D(16x8) += A(16x16) * B(16x8)
__device__ __forceinline__ void mma16(float c[4], const uint32_t a[4],
                                      uint32_t b0, uint32_t b1) {
    asm volatile(
        "mma.sync.aligned.m16n8k16.row.col.f32.f16.f16.f32 "
        "{%0,%1,%2,%3}, {%4,%5,%6,%7}, {%8,%9}, {%0,%1,%2,%3};"
        : "+f"(c[0]), "+f"(c[1]), "+f"(c[2]), "+f"(c[3])
        : "r"(a[0]), "r"(a[1]), "r"(a[2]), "r"(a[3]), "r"(b0), "r"(b1));
}

// ---------------------------------------------------------------------------
// fp16 mma.sync GEMM (R13 best config — unchanged):
// C[M,N] = alpha * A[M,K] @ B[N,K]^T (+bias). CTA 128x64, BK=64, 3-stage
// cp.async, 128 threads, 4 warps of 64x32, 3 CTAs/SM, frag double-buffer.
// ---------------------------------------------------------------------------
constexpr int BM = 128, BN = 64, BK = 64, STAGES = 3;
constexpr int ATILE   = BM * BK * 2;            // 16 KB
constexpr int BTILE   = BN * BK * 2;            //  8 KB
constexpr int STAGE_B = ATILE + BTILE;          // 24 KB
constexpr int GEMM_SMEM = STAGES * STAGE_B + 1024;   // 73.75 KB

template <bool BIAS, bool OUTHALF>
__global__ __launch_bounds__(128, 3)
void gemm_tc(const __half* __restrict__ Ag, const __half* __restrict__ Bg,
             void* __restrict__ Cg, const float* __restrict__ bias,
             int lda, int ldb, int ldc,
             long long sA, long long sB, long long sC,
             int K, float alpha)
{
    extern __shared__ char smem_raw[];
    const uint32_t sb = (s2u(smem_raw) + 1023u) & ~1023u;

    const int tid = threadIdx.x, lane = tid & 31, wid = tid >> 5;
    const int wm = wid & 1;          // 0..1 : 64-row slab
    const int wn = wid >> 1;         // 0..1 : 32-col slab
    const int m0 = blockIdx.y * BM, n0 = blockIdx.x * BN;

    const __half* A = Ag + (size_t)blockIdx.z * sA;
    const __half* B = Bg + (size_t)blockIdx.z * sB;
    const int nk = K / BK;

    const int r0 = tid >> 3;                   // 0..15
    const int kq = tid & 7;
    const uint32_t scol = ((uint32_t)(kq * 16)) ^ ((uint32_t)((r0 & 7) << 4));

    const __half* Arow = A + (size_t)(m0 + r0) * lda + kq * 8;
    const __half* Brow = B + (size_t)(n0 + r0) * ldb + kq * 8;

    const int  rbase = lane & 15;
    const uint32_t xorv = (uint32_t)((lane & 7) << 4);
    const uint32_t kq16 = (uint32_t)((lane >> 4) << 4);   // 0 or 16 bytes

    float acc[4][4][4];
#pragma unroll
    for (int a = 0; a < 4; a++)
#pragma unroll
        for (int b = 0; b < 4; b++)
#pragma unroll
            for (int c = 0; c < 4; c++) acc[a][b][c] = 0.0f;

#define LOAD_STAGE(s, kc)                                                      \
    do {                                                                       \
        const uint32_t ab = sb + (s) * STAGE_B;                                \
        const __half* ap = Arow + (size_t)(kc) * BK;                           \
        const __half* bp = Brow + (size_t)(kc) * BK;                           \
        _Pragma("unroll")                                                      \
        for (int i = 0; i < 8; i++)                                            \
            cpa16(ab + (uint32_t)((r0 + 16 * i) * 128) + scol,                 \
                  ap + (size_t)(16 * i) * lda);                                \
        _Pragma("unroll")                                                      \
        for (int i = 0; i < 4; i++)                                            \
            cpa16(ab + ATILE + (uint32_t)((r0 + 16 * i) * 128) + scol,         \
                  bp + (size_t)(16 * i) * ldb);                                \
    } while (0)

    LOAD_STAGE(0, 0);
    asm volatile("cp.async.commit_group;");
    LOAD_STAGE(1, 1);
    asm volatile("cp.async.commit_group;");

    for (int kc = 0; kc < nk; kc++) {
        asm volatile("cp.async.wait_group 1;");
        __syncthreads();

        if (kc + 2 < nk) {
            const int s = (kc + 2) % STAGES;
            LOAD_STAGE(s, kc + 2);
        }
        asm volatile("cp.async.commit_group;");

        const uint32_t stg = sb + (kc % STAGES) * STAGE_B;
        const uint32_t aB = stg + (uint32_t)((wm * 64 + rbase) * 128);
        const uint32_t bB = stg + ATILE + (uint32_t)((wn * 32 + rbase) * 128);

        uint32_t af[2][4][4], bf[2][2][4];
        {
            const uint32_t kt0 = kq16 ^ xorv;
#pragma unroll
            for (int mt = 0; mt < 4; mt++) ldsm4(af[0][mt], aB + mt * 16 * 128 + kt0);
#pragma unroll
            for (int bp = 0; bp < 2; bp++) ldsm4(bf[0][bp], bB + bp * 16 * 128 + kt0);
        }
#pragma unroll
        for (int ks = 0; ks < 4; ks++) {
            const int cur = ks & 1, nxt = cur ^ 1;
            if (ks < 3) {
                const uint32_t kt = ((uint32_t)((ks + 1) * 32) + kq16) ^ xorv;
#pragma unroll
                for (int mt = 0; mt < 4; mt++) ldsm4(af[nxt][mt], aB + mt * 16 * 128 + kt);
#pragma unroll
                for (int bp = 0; bp < 2; bp++) ldsm4(bf[nxt][bp], bB + bp * 16 * 128 + kt);
            }
#pragma unroll
            for (int mt = 0; mt < 4; mt++)
#pragma unroll
                for (int bp = 0; bp < 2; bp++) {
                    mma16(acc[mt][2 * bp + 0], af[cur][mt], bf[cur][bp][0], bf[cur][bp][2]);
                    mma16(acc[mt][2 * bp + 1], af[cur][mt], bf[cur][bp][1], bf[cur][bp][3]);
                }
        }
    }
#undef LOAD_STAGE

    // ---- epilogue ----
    const int g = lane >> 2, tg = lane & 3;
#pragma unroll
    for (int mt = 0; mt < 4; mt++) {
        const size_t rw0 = (size_t)(m0 + wm * 64 + mt * 16 + g) * ldc;
        const size_t rw1 = rw0 + (size_t)8 * ldc;
#pragma unroll
        for (int nn = 0; nn < 4; nn++) {
            const int col = n0 + wn * 32 + nn * 8 + tg * 2;
            float2 v0, v1;
            v0.x = acc[mt][nn][0] * alpha;
            v0.y = acc[mt][nn][1] * alpha;
            v1.x = acc[mt][nn][2] * alpha;
            v1.y = acc[mt][nn][3] * alpha;
            if (BIAS) {
                const float b0 = bias[col], b1 = bias[col + 1];
                v0.x += b0; v0.y += b1;
                v1.x += b0; v1.y += b1;
            }
            if (OUTHALF) {
                __half* C = (__half*)Cg + (size_t)blockIdx.z * sC;
                *(__half2*)(C + rw0 + col) = __floats2half2_rn(v0.x, v0.y);
                *(__half2*)(C + rw1 + col) = __floats2half2_rn(v1.x, v1.y);
            } else {
                float* C = (float*)Cg + (size_t)blockIdx.z * sC;
                *(float2*)(C + rw0 + col) = v0;
                *(float2*)(C + rw1 + col) = v1;
            }
        }
    }
}

// ---------------------------------------------------------------------------
// fp32 -> fp16 copy (for x)
// ---------------------------------------------------------------------------
__global__ void f2h_copy(const float4* __restrict__ in, uint2* __restrict__ out, int n4)
{
    for (int i = blockIdx.x * blockDim.x + threadIdx.x; i < n4; i += gridDim.x * blockDim.x) {
        float4 v = in[i];
        uint2 o;
        o.x = h2_as_u32(__floats2half2_rn(v.x, v.y));
        o.y = h2_as_u32(__floats2half2_rn(v.z, v.w));
        out[i] = o;
    }
}

// ---------------------------------------------------------------------------
// Tiled transpose, float src -> half dst  (weights)
// ---------------------------------------------------------------------------
__global__ void transpose_f2h(const float* __restrict__ src, __half* __restrict__ dst,
                              int ldS, int ldD)
{
    __shared__ float t[32][33];
    const int c0 = blockIdx.x * 32, r0 = blockIdx.y * 32;
    const int tx = threadIdx.x, ty = threadIdx.y;
#pragma unroll
    for (int i = 0; i < 32; i += 8)
        t[ty + i][tx] = src[(size_t)(r0 + ty + i) * ldS + c0 + tx];
    __syncthreads();
#pragma unroll
    for (int i = 0; i < 32; i += 8)
        dst[(size_t)(c0 + ty + i) * ldD + r0 + tx] = __float2half_rn(t[tx][ty + i]);
}

// ---------------------------------------------------------------------------
// Tiled transpose, half src -> half dst (V^T), batched
// ---------------------------------------------------------------------------
__global__ void transpose_h2h(const __half* __restrict__ src, __half* __restrict__ dst,
                              int ldS, int ldD, long long sS, long long sD)
{
    __shared__ __half t[32][34];
    src += (size_t)blockIdx.z * sS;
    dst += (size_t)blockIdx.z * sD;
    const int c0 = blockIdx.x * 32, r0 = blockIdx.y * 32;
    const int tx = threadIdx.x, ty = threadIdx.y;
#pragma unroll
    for (int i = 0; i < 32; i += 8)
        t[ty + i][tx] = src[(size_t)(r0 + ty + i) * ldS + c0 + tx];
    __syncthreads();
#pragma unroll
    for (int i = 0; i < 32; i += 8)
        dst[(size_t)(c0 + ty + i) * ldD + r0 + tx] = t[tx][ty + i];
}

// ---------------------------------------------------------------------------
// Fused dual softmax with mask-fill: fp32 scores in, fp16 weights out.
// One CTA per q row of 2048; 256 threads, 8 values each.
// ---------------------------------------------------------------------------
__global__ __launch_bounds__(256)
void dual_softmax_k(const float* __restrict__ scores, const int* __restrict__ mask,
                    __half* __restrict__ wout)
{
    const long long row = blockIdx.x;
    const float* s = scores + row * 2048;
    const int* mk = mask + row * 2048;
    __half* o = wout + row * 2048;
    const int tid = threadIdx.x;

    float v[8];
    int m[8];
#pragma unroll
    for (int i = 0; i < 8; ++i) {
        v[i] = s[tid + (i << 8)];
        m[i] = mk[tid + (i << 8)];
    }

    __shared__ float sred[8];

    // softmax 1: max
    float x = -3.0e38f;
#pragma unroll
    for (int i = 0; i < 8; ++i) x = fmaxf(x, v[i]);
#pragma unroll
    for (int ofs = 16; ofs > 0; ofs >>= 1) x = fmaxf(x, __shfl_xor_sync(0xffffffffu, x, ofs));
    if ((tid & 31) == 0) sred[tid >> 5] = x;
    __syncthreads();
    if (tid == 0) {
        float y = sred[0];
#pragma unroll
        for (int w = 1; w < 8; ++w) y = fmaxf(y, sred[w]);
        sred[0] = y;
    }
    __syncthreads();
    const float m1 = sred[0];
    __syncthreads();

    // softmax 1: exp + sum
    float su = 0.0f;
#pragma unroll
    for (int i = 0; i < 8; ++i) {
        v[i] = __expf(v[i] - m1);
        su += v[i];
    }
#pragma unroll
    for (int ofs = 16; ofs > 0; ofs >>= 1) su += __shfl_xor_sync(0xffffffffu, su, ofs);
    if ((tid & 31) == 0) sred[tid >> 5] = su;
    __syncthreads();
    if (tid == 0) {
        float y = 0.0f;
#pragma unroll
        for (int w = 0; w < 8; ++w) y += sred[w];
        sred[0] = y;
    }
    __syncthreads();
    const float inv1 = 1.0f / sred[0];
    __syncthreads();

#pragma unroll
    for (int i = 0; i < 8; ++i) v[i] *= inv1;

    // softmax 2: masked max
    float x2 = -1.0e30f;
#pragma unroll
    for (int i = 0; i < 8; ++i)
        if (m[i]) x2 = fmaxf(x2, v[i]);
#pragma unroll
    for (int ofs = 16; ofs > 0; ofs >>= 1) x2 = fmaxf(x2, __shfl_xor_sync(0xffffffffu, x2, ofs));
    if ((tid & 31) == 0) sred[tid >> 5] = x2;
    __syncthreads();
    if (tid == 0) {
        float y = sred[0];
#pragma unroll
        for (int w = 1; w < 8; ++w) y = fmaxf(y, sred[w]);
        sred[0] = y;
    }
    __syncthreads();
    const float m2 = sred[0];
    __syncthreads();

    if (m2 < -1.0e29f) {
        const __half u = __float2half_rn(1.0f / 2048.0f);
#pragma unroll
        for (int i = 0; i < 8; ++i) o[tid + (i << 8)] = u;
        return;
    }

    // softmax 2: masked exp + sum
    float su2 = 0.0f;
#pragma unroll
    for (int i = 0; i < 8; ++i) {
        const float e = m[i] ? __expf(v[i] - m2) : 0.0f;
        v[i] = e;
        su2 += e;
    }
#pragma unroll
    for (int ofs = 16; ofs > 0; ofs >>= 1) su2 += __shfl_xor_sync(0xffffffffu, su2, ofs);
    if ((tid & 31) == 0) sred[tid >> 5] = su2;
    __syncthreads();
    if (tid == 0) {
        float y = 0.0f;
#pragma unroll
        for (int w = 0; w < 8; ++w) y += sred[w];
        sred[0] = y;
    }
    __syncthreads();
    const float inv2 = 1.0f / sred[0];

#pragma unroll
    for (int i = 0; i < 8; ++i) o[tid + (i << 8)] = __float2half_rn(v[i] * inv2);
}

// ---------------------------------------------------------------------------
// Launch: batch-pipelined across 3 stream lanes (retry of R14 after infra
// flake — capture-legal fork/join via events recorded before waits).
//   default: head conversions, QKV GEMM, scores_0..7
//   s1     : vT transpose, softmax_b (as each scores_b completes)
//   s2     : att_b -> out_b (as each softmax_b completes)
// Streams/events are created ONCE on the first (uncaptured correctness) call
// and reused; resource handles only — identical recorded work every call.
// ---------------------------------------------------------------------------
extern "C" void kernel_launch(void* const* d_in, const int* in_sizes, int n_in,
                              void* d_out, int out_size)
{
    (void)in_sizes; (void)n_in; (void)out_size;

    const float* x     = (const float*)d_in[0];
    const int*   mask  = (const int*)d_in[1];
    const float* W_qkv = (const float*)d_in[2];
    const float* b_qkv = (const float*)d_in[3];
    const float* W_out = (const float*)d_in[4];
    const float* b_out = (const float*)d_in[5];
    float* out = (float*)d_out;

    __half *xh, *qkv, *wbuf, *att, *vT, *wqkvT, *woutT;
    float *scores;
    cudaGetSymbolAddress((void**)&xh, g_xh);
    cudaGetSymbolAddress((void**)&qkv, g_qkv);
    cudaGetSymbolAddress((void**)&scores, g_scores);
    cudaGetSymbolAddress((void**)&wbuf, g_w);
    cudaGetSymbolAddress((void**)&att, g_att);
    cudaGetSymbolAddress((void**)&vT, g_vT);
    cudaGetSymbolAddress((void**)&wqkvT, g_wqkvT);
    cudaGetSymbolAddress((void**)&woutT, g_woutT);

    static bool s_init = false;
    static cudaStream_t s1, s2;
    static cudaEvent_t evQ, evS[BBATCH], evM[BBATCH], evFin;
    if (!s_init) {
        cudaStreamCreateWithFlags(&s1, cudaStreamNonBlocking);
        cudaStreamCreateWithFlags(&s2, cudaStreamNonBlocking);
        cudaEventCreateWithFlags(&evQ, cudaEventDisableTiming);
        cudaEventCreateWithFlags(&evFin, cudaEventDisableTiming);
        for (int b = 0; b < BBATCH; b++) {
            cudaEventCreateWithFlags(&evS[b], cudaEventDisableTiming);
            cudaEventCreateWithFlags(&evM[b], cudaEventDisableTiming);
        }
        cudaFuncSetAttribute(gemm_tc<true,  true >, cudaFuncAttributeMaxDynamicSharedMemorySize, GEMM_SMEM);
        cudaFuncSetAttribute(gemm_tc<false, false>, cudaFuncAttributeMaxDynamicSharedMemorySize, GEMM_SMEM);
        cudaFuncSetAttribute(gemm_tc<false, true >, cudaFuncAttributeMaxDynamicSharedMemorySize, GEMM_SMEM);
        cudaFuncSetAttribute(gemm_tc<true,  false>, cudaFuncAttributeMaxDynamicSharedMemorySize, GEMM_SMEM);
        s_init = true;
    }

    const int ROWS = BBATCH * SEQ;                     // 16384
    const long long sQKV = (long long)SEQ * 3 * DIM;
    const long long sSC  = (long long)SEQ * SEQ;
    const long long sAT  = (long long)SEQ * DIM;
    const long long sVT  = (long long)DIM * SEQ;

    // ---- default stream: head + QKV ----
    f2h_copy<<<4096, 256, 0, 0>>>((const float4*)x, (uint2*)xh, ROWS * DIM / 4);
    transpose_f2h<<<dim3(3 * DIM / 32, DIM / 32, 1), dim3(32, 8), 0, 0>>>(
        W_qkv, wqkvT, 3 * DIM, DIM);
    transpose_f2h<<<dim3(DIM / 32, DIM / 32, 1), dim3(32, 8), 0, 0>>>(
        W_out, woutT, DIM, DIM);

    gemm_tc<true, true><<<dim3(3 * DIM / BN, ROWS / BM, 1), 128, GEMM_SMEM, 0>>>(
        xh, wqkvT, qkv, b_qkv, DIM, DIM, 3 * DIM, 0, 0, 0, DIM, 1.0f);
    cudaEventRecord(evQ, 0);

    // ---- s1: V^T transpose overlaps scores_0 ----
    cudaStreamWaitEvent(s1, evQ, 0);
    transpose_h2h<<<dim3(DIM / 32, SEQ / 32, BBATCH), dim3(32, 8), 0, s1>>>(
        qkv + 2 * DIM, vT, 3 * DIM, SEQ, sQKV, sVT);

    for (int b = 0; b < BBATCH; b++) {
        // scores_b on default
        gemm_tc<false, false><<<dim3(SEQ / BN, SEQ / BM, 1), 128, GEMM_SMEM, 0>>>(
            qkv + (size_t)b * sQKV, qkv + DIM + (size_t)b * sQKV,
            scores + (size_t)b * sSC, nullptr,
            3 * DIM, 3 * DIM, SEQ, 0, 0, 0, DIM, 0.03125f);
        cudaEventRecord(evS[b], 0);

        // softmax_b on s1 (also ordered after vT by stream order)
        cudaStreamWaitEvent(s1, evS[b], 0);
        dual_softmax_k<<<SEQ, 256, 0, s1>>>(
            scores + (size_t)b * sSC, mask + (size_t)b * sSC, wbuf + (size_t)b * sSC);
        cudaEventRecord(evM[b], s1);

        // att_b -> out_b on s2
        cudaStreamWaitEvent(s2, evM[b], 0);
        gemm_tc<false, true><<<dim3(DIM / BN, SEQ / BM, 1), 128, GEMM_SMEM, s2>>>(
            wbuf + (size_t)b * sSC, vT + (size_t)b * sVT,
            att + (size_t)b * sAT, nullptr,
            SEQ, SEQ, DIM, 0, 0, 0, SEQ, 1.0f);
        gemm_tc<true, false><<<dim3(DIM / BN, SEQ / BM, 1), 128, GEMM_SMEM, s2>>>(
            att + (size_t)b * sAT, woutT,
            out + (size_t)b * sAT, b_out,
            DIM, DIM, DIM, 0, 0, 0, DIM, 1.0f);
    }

    // join everything back to the default stream
    cudaEventRecord(evFin, s2);
    cudaStreamWaitEvent(0, evFin, 0);
}